// round 7
// baseline (speedup 1.0000x reference)
// FlashSparseAttention — round 6: 256x128-tile 4-stage mma.sync bf16x3 GEMMs
// (fused QKV launch) + fp32 SIMT flash attention.
// B=2, S=2048, H=2048, NH=16, NKV=4, HD=128, GQA groups=4, RoPE theta=1e4.
#include <cuda_runtime.h>
#include <cuda_bf16.h>
#include <math.h>
#include <stdint.h>

#define B_    2
#define S_    2048
#define H_    2048
#define NH_   16
#define NKV_  4
#define HD_   128
#define M_    (B_*S_)      // 4096 rows

// ---------------- scratch (device globals: allocation-free) ----------------
__device__ float g_q [(size_t)M_*NH_*HD_];    // 32 MB
__device__ float g_k [(size_t)M_*NKV_*HD_];   // 8 MB
__device__ float g_v [(size_t)M_*NKV_*HD_];   // 8 MB
__device__ float g_ao[(size_t)M_*NH_*HD_];    // 32 MB
__device__ float g_cos[S_*64];
__device__ float g_sin[S_*64];

// bf16 hi/lo splits
__device__ __nv_bfloat16 g_ah [(size_t)M_*H_],   g_al [(size_t)M_*H_];
__device__ __nv_bfloat16 g_wqh[(size_t)2048*H_], g_wql[(size_t)2048*H_];
__device__ __nv_bfloat16 g_wkh[(size_t)512*H_],  g_wkl[(size_t)512*H_];
__device__ __nv_bfloat16 g_wvh[(size_t)512*H_],  g_wvl[(size_t)512*H_];
__device__ __nv_bfloat16 g_woh[(size_t)2048*H_], g_wol[(size_t)2048*H_];
__device__ __nv_bfloat16 g_aoh[(size_t)M_*2048], g_aol[(size_t)M_*2048];

// ---------------- PTX helpers ------------------------------------------------
__device__ __forceinline__ uint32_t smem_u32(const void* p) {
    uint32_t a;
    asm("{ .reg .u64 t; cvta.to.shared.u64 t, %1; cvt.u32.u64 %0, t; }" : "=r"(a) : "l"(p));
    return a;
}
#define CP_ASYNC16(dst, src) \
    asm volatile("cp.async.cg.shared.global [%0], [%1], 16;" :: "r"(dst), "l"(src) : "memory")
#define CP_COMMIT()  asm volatile("cp.async.commit_group;" ::: "memory")
#define CP_WAIT2()   asm volatile("cp.async.wait_group 2;" ::: "memory")

#define LDSM_X4(r0, r1, r2, r3, addr) \
    asm volatile("ldmatrix.sync.aligned.m8n8.x4.shared.b16 {%0,%1,%2,%3}, [%4];" \
        : "=r"(r0), "=r"(r1), "=r"(r2), "=r"(r3) : "r"(addr))

#define MMA_BF16(d, a, b0, b1) \
    asm volatile("mma.sync.aligned.m16n8k16.row.col.f32.bf16.bf16.f32 " \
        "{%0,%1,%2,%3}, {%4,%5,%6,%7}, {%8,%9}, {%0,%1,%2,%3};" \
        : "+f"((d)[0]), "+f"((d)[1]), "+f"((d)[2]), "+f"((d)[3]) \
        : "r"((a)[0]), "r"((a)[1]), "r"((a)[2]), "r"((a)[3]), "r"(b0), "r"(b1))

// ---------------- bf16 split kernel -----------------------------------------
__device__ __forceinline__ void split1(float x, __nv_bfloat16& h, __nv_bfloat16& l) {
    h = __float2bfloat16(x);
    l = __float2bfloat16(x - __bfloat162float(h));
}
__global__ void split_bf16(const float* __restrict__ srcp, int sel, int n)
{
    int i = (blockIdx.x * blockDim.x + threadIdx.x) * 4;
    if (i >= n) return;
    const float* src; __nv_bfloat16 *hi, *lo;
    switch (sel) {
        case 0: src = srcp; hi = g_ah;  lo = g_al;  break;
        case 1: src = srcp; hi = g_wqh; lo = g_wql; break;
        case 2: src = srcp; hi = g_wkh; lo = g_wkl; break;
        case 3: src = srcp; hi = g_wvh; lo = g_wvl; break;
        case 4: src = srcp; hi = g_woh; lo = g_wol; break;
        default: src = g_ao; hi = g_aoh; lo = g_aol; break;
    }
    float4 v = *(const float4*)(src + i);
    __nv_bfloat16 h0, l0, h1, l1, h2, l2, h3, l3;
    split1(v.x, h0, l0); split1(v.y, h1, l1);
    split1(v.z, h2, l2); split1(v.w, h3, l3);
    *(__nv_bfloat162*)(hi + i)     = __nv_bfloat162(h0, h1);
    *(__nv_bfloat162*)(hi + i + 2) = __nv_bfloat162(h2, h3);
    *(__nv_bfloat162*)(lo + i)     = __nv_bfloat162(l0, l1);
    *(__nv_bfloat162*)(lo + i + 2) = __nv_bfloat162(l2, l3);
}

// ---------------- mma.sync bf16x3 GEMM, 256x128 tile, 4-stage ----------------
// C[M,N] = A[M,K] * W[N,K]^T with A = Ah+Al, W = Bh+Bl (drop Al*Bl term).
// 256 thr = 8 warps (4m x 2n), warp tile 64x64, BK=32.
// Smem stage: Ah(16K)|Al(16K)|Bh(8K)|Bl(8K) = 48KB, 4 stages = 192KB.
#define BKK       32
#define NKI       (H_/BKK)          // 64 k-iterations
#define A_SPLIT_B 16384             // 256 rows x 64 B
#define B_SPLIT_B 8192              // 128 rows x 64 B
#define STAGE_B   49152
#define NSTAGES   4
#define GEMM_SMEM (NSTAGES*STAGE_B) // 196608

__device__ __forceinline__ uint32_t sw_off(int row, int chunk) {
    return (uint32_t)(row * 64 + ((chunk ^ ((row >> 1) & 3)) << 4));
}

__global__ __launch_bounds__(256) void tc_gemm(int which, float* Cout)
{
    extern __shared__ char smem[];
    const uint32_t sb0 = smem_u32(smem);
    const int tid = threadIdx.x;
    const int wid = tid >> 5, lane = tid & 31;
    const int wm = wid & 3, wn = wid >> 2;        // 4(m) x 2(n) warp grid

    const int m0 = blockIdx.y * 256, n0 = blockIdx.x * 128;

    const __nv_bfloat16 *Ahp, *Alp, *Bhp, *Blp;
    float* C; int Nc, nb;
    if (which == 0) {                              // fused QKV, global n in [0,3072)
        Ahp = g_ah; Alp = g_al;
        if (n0 < 2048)      { Bhp = g_wqh + (size_t)n0 * H_;        Blp = g_wql + (size_t)n0 * H_;        C = g_q; Nc = 2048; nb = n0; }
        else if (n0 < 2560) { Bhp = g_wkh + (size_t)(n0-2048) * H_; Blp = g_wkl + (size_t)(n0-2048) * H_; C = g_k; Nc = 512;  nb = n0 - 2048; }
        else                { Bhp = g_wvh + (size_t)(n0-2560) * H_; Blp = g_wvl + (size_t)(n0-2560) * H_; C = g_v; Nc = 512;  nb = n0 - 2560; }
    } else {                                       // O projection
        Ahp = g_aoh; Alp = g_aol;
        Bhp = g_woh + (size_t)n0 * H_; Blp = g_wol + (size_t)n0 * H_;
        C = Cout; Nc = 2048; nb = n0;
    }

    // stage load: 3072 x 16B chunks; A: 2048 (2 splits x 256 rows x 4), B: 1024.
    auto load_stage = [&](int kt, int s) {
        const int k0 = kt * BKK;
        const uint32_t stage = sb0 + s * STAGE_B;
#pragma unroll
        for (int i = 0; i < 12; ++i) {
            int ch = tid + (i << 8);
            if (ch < 2048) {
                int sp = ch >> 10, w = ch & 1023;
                int r = w >> 2, c = w & 3;
                const __nv_bfloat16* src = (sp ? Alp : Ahp) + (size_t)(m0 + r) * H_ + k0 + c * 8;
                CP_ASYNC16(stage + sp * A_SPLIT_B + sw_off(r, c), src);
            } else {
                int ch2 = ch - 2048;
                int sp = ch2 >> 9, w = ch2 & 511;
                int r = w >> 2, c = w & 3;
                const __nv_bfloat16* src = (sp ? Blp : Bhp) + (size_t)r * H_ + k0 + c * 8;
                CP_ASYNC16(stage + 2 * A_SPLIT_B + sp * B_SPLIT_B + sw_off(r, c), src);
            }
        }
        CP_COMMIT();
    };

    float acc[4][8][4];
#pragma unroll
    for (int mi = 0; mi < 4; mi++)
#pragma unroll
        for (int ni = 0; ni < 8; ni++)
#pragma unroll
            for (int e = 0; e < 4; e++) acc[mi][ni][e] = 0.f;

    load_stage(0, 0);
    load_stage(1, 1);
    load_stage(2, 2);

    const int lrow = lane & 15;
    const int lchunk = lane >> 4;

    for (int kt = 0; kt < NKI; ++kt) {
        CP_WAIT2();             // stage kt complete (this thread's groups)
        __syncthreads();        // all threads' stage-kt chunks visible; prev compute done
        if (kt + 3 < NKI) load_stage(kt + 3, (kt + 3) & 3);
        else              CP_COMMIT();   // keep group count semantics stable

        const uint32_t stage = sb0 + (kt & 3) * STAGE_B;

#pragma unroll
        for (int kk = 0; kk < 2; ++kk) {
            const int cc = kk * 2 + lchunk;
            uint32_t AHf[4][4], ALf[4][4];
#pragma unroll
            for (int mi = 0; mi < 4; ++mi) {
                int row = wm * 64 + mi * 16 + lrow;
                uint32_t a = stage + sw_off(row, cc);
                LDSM_X4(AHf[mi][0], AHf[mi][1], AHf[mi][2], AHf[mi][3], a);
                LDSM_X4(ALf[mi][0], ALf[mi][1], ALf[mi][2], ALf[mi][3], a + A_SPLIT_B);
            }
            uint32_t BHf[4][4], BLf[4][4];
#pragma unroll
            for (int g = 0; g < 4; ++g) {
                int row = wn * 64 + g * 16 + lrow;
                uint32_t a = stage + 2 * A_SPLIT_B + sw_off(row, cc);
                LDSM_X4(BHf[g][0], BHf[g][1], BHf[g][2], BHf[g][3], a);
                LDSM_X4(BLf[g][0], BLf[g][1], BLf[g][2], BLf[g][3], a + B_SPLIT_B);
            }
            // B frag pairing (verified R5): n-block sub -> (r[sub], r[sub+2])
#pragma unroll
            for (int mi = 0; mi < 4; ++mi)
#pragma unroll
                for (int ni = 0; ni < 8; ++ni) {
                    const int g = ni >> 1, sub = ni & 1;
                    MMA_BF16(acc[mi][ni], AHf[mi], BHf[g][sub], BHf[g][sub + 2]);
                    MMA_BF16(acc[mi][ni], AHf[mi], BLf[g][sub], BLf[g][sub + 2]);
                    MMA_BF16(acc[mi][ni], ALf[mi], BHf[g][sub], BHf[g][sub + 2]);
                }
        }
    }

    // epilogue
#pragma unroll
    for (int mi = 0; mi < 4; ++mi) {
        const int row = m0 + wm * 64 + mi * 16 + (lane >> 2);
#pragma unroll
        for (int ni = 0; ni < 8; ++ni) {
            const int col = nb + wn * 64 + ni * 8 + (lane & 3) * 2;
            float* cp = C + (size_t)row * Nc + col;
            *(float2*)cp = make_float2(acc[mi][ni][0], acc[mi][ni][1]);
            *(float2*)(cp + (size_t)8 * Nc) = make_float2(acc[mi][ni][2], acc[mi][ni][3]);
        }
    }
}

// ---------------- RoPE table (double precision trig) ------------------------
__global__ void rope_table_kernel()
{
    int idx = blockIdx.x * blockDim.x + threadIdx.x;
    if (idx >= S_ * 64) return;
    int s = idx >> 6, i = idx & 63;
    double inv = pow(10000.0, -(double)(2 * i) / 128.0);
    double f = (double)s * inv;
    g_cos[idx] = (float)cos(f);
    g_sin[idx] = (float)sin(f);
}

// ---------------- RoPE apply (in place on g_q or g_k) -----------------------
__global__ void rope_apply(int which, int nheads, int total)
{
    int idx = blockIdx.x * blockDim.x + threadIdx.x;
    if (idx >= total) return;
    float* x = (which == 1) ? g_q : g_k;
    int i = idx & 63;
    int h = (idx >> 6) % nheads;
    int m = idx / (64 * nheads);
    int s = m & (S_ - 1);
    float c  = g_cos[s * 64 + i];
    float sn = g_sin[s * 64 + i];
    float* p = x + ((size_t)m * nheads + h) * HD_;
    float x1 = p[i], x2 = p[i + 64];
    p[i]      = x1 * c - x2 * sn;
    p[i + 64] = x2 * c + x1 * sn;
}

// ---------------- fp32 causal flash attention --------------------------------
#define BR 64
#define BC 64
#define QSTR 132
#define PSTR 68
#define FLASH_SMEM ((2*BR*QSTR + BR*PSTR) * (int)sizeof(float))

__global__ __launch_bounds__(256, 2) void flash_attn()
{
    extern __shared__ float sm[];
    float* Qs = sm;
    float* Ks = sm + BR * QSTR;
    float* Ps = sm + 2 * BR * QSTR;

    const int tid = threadIdx.x;
    const int tx = tid & 15, ty = tid >> 4;
    const int qb = blockIdx.x, h = blockIdx.y, b = blockIdx.z;
    const int hk = h >> 2;
    const int q0 = qb * BR;

    const float* Qg = g_q + (((size_t)b * S_ + q0) * NH_ + h) * HD_;
#pragma unroll 4
    for (int idx = tid; idx < BR * 32; idx += 256) {
        int r = idx >> 5, c4 = idx & 31;
        *(float4*)&Qs[r * QSTR + c4 * 4] =
            *(const float4*)(Qg + (size_t)r * (NH_ * HD_) + c4 * 4);
    }

    float m_i[4], l_i[4], acc[4][8];
#pragma unroll
    for (int i = 0; i < 4; i++) {
        m_i[i] = -INFINITY; l_i[i] = 0.f;
#pragma unroll
        for (int c = 0; c < 8; c++) acc[i][c] = 0.f;
    }

    const float scale = 0.08838834764831845f;

    for (int jb = 0; jb <= qb; jb++) {
        const int j0 = jb * BC;

        const float* Kg = g_k + (((size_t)b * S_ + j0) * NKV_ + hk) * HD_;
#pragma unroll 4
        for (int idx = tid; idx < BC * 32; idx += 256) {
            int r = idx >> 5, c4 = idx & 31;
            *(float4*)&Ks[r * QSTR + c4 * 4] =
                *(const float4*)(Kg + (size_t)r * (NKV_ * HD_) + c4 * 4);
        }
        __syncthreads();

        float sv[4][4];
#pragma unroll
        for (int i = 0; i < 4; i++)
#pragma unroll
            for (int jj = 0; jj < 4; jj++) sv[i][jj] = 0.f;

        for (int d4 = 0; d4 < 32; d4++) {
            float4 qv[4], kvv[4];
#pragma unroll
            for (int i = 0; i < 4; i++)
                qv[i] = *(const float4*)&Qs[(ty * 4 + i) * QSTR + d4 * 4];
#pragma unroll
            for (int jj = 0; jj < 4; jj++)
                kvv[jj] = *(const float4*)&Ks[(tx + 16 * jj) * QSTR + d4 * 4];
#pragma unroll
            for (int i = 0; i < 4; i++)
#pragma unroll
                for (int jj = 0; jj < 4; jj++) {
                    sv[i][jj] = fmaf(qv[i].x, kvv[jj].x, sv[i][jj]);
                    sv[i][jj] = fmaf(qv[i].y, kvv[jj].y, sv[i][jj]);
                    sv[i][jj] = fmaf(qv[i].z, kvv[jj].z, sv[i][jj]);
                    sv[i][jj] = fmaf(qv[i].w, kvv[jj].w, sv[i][jj]);
                }
        }

        const bool diag = (jb == qb);
#pragma unroll
        for (int i = 0; i < 4; i++) {
            const int row = q0 + ty * 4 + i;
            float mx = -INFINITY;
#pragma unroll
            for (int jj = 0; jj < 4; jj++) {
                float x = sv[i][jj] * scale;
                if (diag && (j0 + tx + 16 * jj) > row) x = -INFINITY;
                sv[i][jj] = x;
                mx = fmaxf(mx, x);
            }
#pragma unroll
            for (int off = 8; off; off >>= 1)
                mx = fmaxf(mx, __shfl_xor_sync(0xffffffffu, mx, off));
            float mnew = fmaxf(m_i[i], mx);
            float corr = __expf(m_i[i] - mnew);
            float rs = 0.f;
#pragma unroll
            for (int jj = 0; jj < 4; jj++) {
                float p = __expf(sv[i][jj] - mnew);
                sv[i][jj] = p;
                rs += p;
            }
#pragma unroll
            for (int off = 8; off; off >>= 1)
                rs += __shfl_xor_sync(0xffffffffu, rs, off);
            l_i[i] = l_i[i] * corr + rs;
            m_i[i] = mnew;
#pragma unroll
            for (int c = 0; c < 8; c++) acc[i][c] *= corr;
#pragma unroll
            for (int jj = 0; jj < 4; jj++)
                Ps[(ty * 4 + i) * PSTR + tx + 16 * jj] = sv[i][jj];
        }
        __syncthreads();

        const float* Vg = g_v + (((size_t)b * S_ + j0) * NKV_ + hk) * HD_;
#pragma unroll 4
        for (int idx = tid; idx < BC * 32; idx += 256) {
            int r = idx >> 5, c4 = idx & 31;
            *(float4*)&Ks[r * QSTR + c4 * 4] =
                *(const float4*)(Vg + (size_t)r * (NKV_ * HD_) + c4 * 4);
        }
        __syncthreads();

#pragma unroll 4
        for (int j = 0; j < BC; j++) {
            float pv[4];
#pragma unroll
            for (int i = 0; i < 4; i++) pv[i] = Ps[(ty * 4 + i) * PSTR + j];
            float4 v0 = *(const float4*)&Ks[j * QSTR + tx * 8];
            float4 v1 = *(const float4*)&Ks[j * QSTR + tx * 8 + 4];
            float vv[8] = {v0.x, v0.y, v0.z, v0.w, v1.x, v1.y, v1.z, v1.w};
#pragma unroll
            for (int i = 0; i < 4; i++)
#pragma unroll
                for (int c = 0; c < 8; c++)
                    acc[i][c] = fmaf(pv[i], vv[c], acc[i][c]);
        }
        __syncthreads();
    }

#pragma unroll
    for (int i = 0; i < 4; i++) {
        float inv = 1.0f / l_i[i];
        float* Og = g_ao + (((size_t)b * S_ + q0 + ty * 4 + i) * NH_ + h) * HD_ + tx * 8;
        float4 o0 = make_float4(acc[i][0] * inv, acc[i][1] * inv, acc[i][2] * inv, acc[i][3] * inv);
        float4 o1 = make_float4(acc[i][4] * inv, acc[i][5] * inv, acc[i][6] * inv, acc[i][7] * inv);
        *(float4*)Og = o0;
        *(float4*)(Og + 4) = o1;
    }
}

// ---------------- launch ----------------------------------------------------
extern "C" void kernel_launch(void* const* d_in, const int* in_sizes, int n_in,
                              void* d_out, int out_size)
{
    (void)in_sizes; (void)n_in; (void)out_size;
    const float* hs = (const float*)d_in[0];
    const float* Wq = (const float*)d_in[1];
    const float* Wk = (const float*)d_in[2];
    const float* Wv = (const float*)d_in[3];
    const float* Wo = (const float*)d_in[4];
    float* out = (float*)d_out;

    cudaFuncSetAttribute(tc_gemm, cudaFuncAttributeMaxDynamicSharedMemorySize, GEMM_SMEM);
    cudaFuncSetAttribute(flash_attn, cudaFuncAttributeMaxDynamicSharedMemorySize, FLASH_SMEM);

    rope_table_kernel<<<(S_ * 64 + 255) / 256, 256>>>();

    // bf16 hi/lo splits
    {
        int n;
        n = M_ * H_;      split_bf16<<<n / 4 / 256, 256>>>(hs, 0, n);
        n = 2048 * H_;    split_bf16<<<n / 4 / 256, 256>>>(Wq, 1, n);
        n = 512 * H_;     split_bf16<<<n / 4 / 256, 256>>>(Wk, 2, n);
        n = 512 * H_;     split_bf16<<<n / 4 / 256, 256>>>(Wv, 3, n);
        n = 2048 * H_;    split_bf16<<<n / 4 / 256, 256>>>(Wo, 4, n);
    }

    // Fused QKV projection: N = 2048(Q) + 512(K) + 512(V) = 3072
    tc_gemm<<<dim3(24, 16), 256, GEMM_SMEM>>>(0, nullptr);

    // RoPE
    int tq = M_ * NH_ * 64;
    rope_apply<<<(tq + 255) / 256, 256>>>(1, NH_, tq);
    int tk = M_ * NKV_ * 64;
    rope_apply<<<(tk + 255) / 256, 256>>>(2, NKV_, tk);

    // Flash attention (fp32 SIMT)
    flash_attn<<<dim3(S_ / BR, NH_, B_), 256, FLASH_SMEM>>>();

    // Output projection
    {
        int n = M_ * 2048;
        split_bf16<<<n / 4 / 256, 256>>>(nullptr, 5, n);
    }
    tc_gemm<<<dim3(16, 16), 256, GEMM_SMEM>>>(1, out);
}

// round 8
// speedup vs baseline: 1.7248x; 1.7248x over previous
// FlashSparseAttention — round 7: tensor-core flash attention (bf16x3) +
// mma.sync bf16x3 GEMMs. RoPE/split fusions; V pre-transposed for PV mma.
// B=2, S=2048, H=2048, NH=16, NKV=4, HD=128, GQA groups=4, RoPE theta=1e4.
#include <cuda_runtime.h>
#include <cuda_bf16.h>
#include <math.h>
#include <stdint.h>

#define B_    2
#define S_    2048
#define H_    2048
#define NH_   16
#define NKV_  4
#define HD_   128
#define M_    (B_*S_)      // 4096 rows

// ---------------- scratch (device globals: allocation-free) ----------------
__device__ float g_q [(size_t)M_*NH_*HD_];    // fp32 QKV-GEMM outputs
__device__ float g_k [(size_t)M_*NKV_*HD_];
__device__ float g_v [(size_t)M_*NKV_*HD_];
__device__ float g_cos[S_*64];
__device__ float g_sin[S_*64];

// bf16 hi/lo splits
__device__ __align__(16) __nv_bfloat16 g_ah [(size_t)M_*H_],   g_al [(size_t)M_*H_];
__device__ __align__(16) __nv_bfloat16 g_wqh[(size_t)2048*H_], g_wql[(size_t)2048*H_];
__device__ __align__(16) __nv_bfloat16 g_wkh[(size_t)512*H_],  g_wkl[(size_t)512*H_];
__device__ __align__(16) __nv_bfloat16 g_wvh[(size_t)512*H_],  g_wvl[(size_t)512*H_];
__device__ __align__(16) __nv_bfloat16 g_woh[(size_t)2048*H_], g_wol[(size_t)2048*H_];
__device__ __align__(16) __nv_bfloat16 g_aoh[(size_t)M_*2048], g_aol[(size_t)M_*2048];
// attention operands (bf16 splits)
__device__ __align__(16) __nv_bfloat16 g_qh [(size_t)M_*NH_*HD_],  g_ql [(size_t)M_*NH_*HD_];
__device__ __align__(16) __nv_bfloat16 g_kh [(size_t)M_*NKV_*HD_], g_kl [(size_t)M_*NKV_*HD_];
__device__ __align__(16) __nv_bfloat16 g_vth[(size_t)M_*NKV_*HD_], g_vtl[(size_t)M_*NKV_*HD_]; // [b][hk][hd][s]

// ---------------- PTX helpers ------------------------------------------------
__device__ __forceinline__ uint32_t smem_u32(const void* p) {
    uint32_t a;
    asm("{ .reg .u64 t; cvta.to.shared.u64 t, %1; cvt.u32.u64 %0, t; }" : "=r"(a) : "l"(p));
    return a;
}
#define CP_ASYNC16(dst, src) \
    asm volatile("cp.async.cg.shared.global [%0], [%1], 16;" :: "r"(dst), "l"(src) : "memory")
#define CP_COMMIT()  asm volatile("cp.async.commit_group;" ::: "memory")
#define CP_WAIT0()   asm volatile("cp.async.wait_group 0;" ::: "memory")
#define CP_WAIT1()   asm volatile("cp.async.wait_group 1;" ::: "memory")
#define CP_WAIT2()   asm volatile("cp.async.wait_group 2;" ::: "memory")

#define LDSM_X4(r0, r1, r2, r3, addr) \
    asm volatile("ldmatrix.sync.aligned.m8n8.x4.shared.b16 {%0,%1,%2,%3}, [%4];" \
        : "=r"(r0), "=r"(r1), "=r"(r2), "=r"(r3) : "r"(addr))

#define MMA_BF16(d, a, b0, b1) \
    asm volatile("mma.sync.aligned.m16n8k16.row.col.f32.bf16.bf16.f32 " \
        "{%0,%1,%2,%3}, {%4,%5,%6,%7}, {%8,%9}, {%0,%1,%2,%3};" \
        : "+f"((d)[0]), "+f"((d)[1]), "+f"((d)[2]), "+f"((d)[3]) \
        : "r"((a)[0]), "r"((a)[1]), "r"((a)[2]), "r"((a)[3]), "r"(b0), "r"(b1))

__device__ __forceinline__ uint32_t sw_off(int row, int chunk) {
    return (uint32_t)(row * 64 + ((chunk ^ ((row >> 1) & 3)) << 4));
}
__device__ __forceinline__ void split_pack(float x0, float x1, uint32_t& h, uint32_t& l) {
    __nv_bfloat16 h0 = __float2bfloat16(x0), h1 = __float2bfloat16(x1);
    __nv_bfloat162 hh; hh.x = h0; hh.y = h1; h = *(uint32_t*)&hh;
    __nv_bfloat162 ll;
    ll.x = __float2bfloat16(x0 - __bfloat162float(h0));
    ll.y = __float2bfloat16(x1 - __bfloat162float(h1));
    l = *(uint32_t*)&ll;
}
__device__ __forceinline__ void store_split2(__nv_bfloat16* hp, __nv_bfloat16* lp,
                                             float a, float b) {
    __nv_bfloat16 ha = __float2bfloat16(a), hb = __float2bfloat16(b);
    __nv_bfloat162 hh; hh.x = ha; hh.y = hb; *(__nv_bfloat162*)hp = hh;
    __nv_bfloat162 ll;
    ll.x = __float2bfloat16(a - __bfloat162float(ha));
    ll.y = __float2bfloat16(b - __bfloat162float(hb));
    *(__nv_bfloat162*)lp = ll;
}

// ---------------- bf16 split kernel (inputs) ---------------------------------
__global__ void split_bf16(const float* __restrict__ srcp, int sel, int n)
{
    int i = (blockIdx.x * blockDim.x + threadIdx.x) * 4;
    if (i >= n) return;
    __nv_bfloat16 *hi, *lo;
    switch (sel) {
        case 0: hi = g_ah;  lo = g_al;  break;
        case 1: hi = g_wqh; lo = g_wql; break;
        case 2: hi = g_wkh; lo = g_wkl; break;
        case 3: hi = g_wvh; lo = g_wvl; break;
        default: hi = g_woh; lo = g_wol; break;
    }
    float4 v = *(const float4*)(srcp + i);
    store_split2(hi + i, lo + i, v.x, v.y);
    store_split2(hi + i + 2, lo + i + 2, v.z, v.w);
}

// ---------------- mma.sync bf16x3 GEMM, 256x128 tile, 4-stage ----------------
#define BKK       32
#define NKI       (H_/BKK)
#define A_SPLIT_B 16384
#define B_SPLIT_B 8192
#define STAGE_B   49152
#define GEMM_SMEM 196608

__global__ __launch_bounds__(256) void tc_gemm(int which, float* Cout)
{
    extern __shared__ char smem[];
    const uint32_t sb0 = smem_u32(smem);
    const int tid = threadIdx.x;
    const int wid = tid >> 5, lane = tid & 31;
    const int wm = wid & 3, wn = wid >> 2;

    const int m0 = blockIdx.y * 256, n0 = blockIdx.x * 128;

    const __nv_bfloat16 *Ahp, *Alp, *Bhp, *Blp;
    float* C; int Nc, nb;
    if (which == 0) {
        Ahp = g_ah; Alp = g_al;
        if (n0 < 2048)      { Bhp = g_wqh + (size_t)n0 * H_;        Blp = g_wql + (size_t)n0 * H_;        C = g_q; Nc = 2048; nb = n0; }
        else if (n0 < 2560) { Bhp = g_wkh + (size_t)(n0-2048) * H_; Blp = g_wkl + (size_t)(n0-2048) * H_; C = g_k; Nc = 512;  nb = n0 - 2048; }
        else                { Bhp = g_wvh + (size_t)(n0-2560) * H_; Blp = g_wvl + (size_t)(n0-2560) * H_; C = g_v; Nc = 512;  nb = n0 - 2560; }
    } else {
        Ahp = g_aoh; Alp = g_aol;
        Bhp = g_woh + (size_t)n0 * H_; Blp = g_wol + (size_t)n0 * H_;
        C = Cout; Nc = 2048; nb = n0;
    }

    auto load_stage = [&](int kt, int s) {
        const int k0 = kt * BKK;
        const uint32_t stage = sb0 + s * STAGE_B;
#pragma unroll
        for (int i = 0; i < 12; ++i) {
            int ch = tid + (i << 8);
            if (ch < 2048) {
                int sp = ch >> 10, w = ch & 1023;
                int r = w >> 2, c = w & 3;
                const __nv_bfloat16* src = (sp ? Alp : Ahp) + (size_t)(m0 + r) * H_ + k0 + c * 8;
                CP_ASYNC16(stage + sp * A_SPLIT_B + sw_off(r, c), src);
            } else {
                int ch2 = ch - 2048;
                int sp = ch2 >> 9, w = ch2 & 511;
                int r = w >> 2, c = w & 3;
                const __nv_bfloat16* src = (sp ? Blp : Bhp) + (size_t)r * H_ + k0 + c * 8;
                CP_ASYNC16(stage + 2 * A_SPLIT_B + sp * B_SPLIT_B + sw_off(r, c), src);
            }
        }
        CP_COMMIT();
    };

    float acc[4][8][4];
#pragma unroll
    for (int mi = 0; mi < 4; mi++)
#pragma unroll
        for (int ni = 0; ni < 8; ni++)
#pragma unroll
            for (int e = 0; e < 4; e++) acc[mi][ni][e] = 0.f;

    load_stage(0, 0);
    load_stage(1, 1);
    load_stage(2, 2);

    const int lrow = lane & 15;
    const int lchunk = lane >> 4;

    for (int kt = 0; kt < NKI; ++kt) {
        CP_WAIT2();
        __syncthreads();
        if (kt + 3 < NKI) load_stage(kt + 3, (kt + 3) & 3);
        else              CP_COMMIT();

        const uint32_t stage = sb0 + (kt & 3) * STAGE_B;

#pragma unroll
        for (int kk = 0; kk < 2; ++kk) {
            const int cc = kk * 2 + lchunk;
            uint32_t AHf[4][4], ALf[4][4];
#pragma unroll
            for (int mi = 0; mi < 4; ++mi) {
                int row = wm * 64 + mi * 16 + lrow;
                uint32_t a = stage + sw_off(row, cc);
                LDSM_X4(AHf[mi][0], AHf[mi][1], AHf[mi][2], AHf[mi][3], a);
                LDSM_X4(ALf[mi][0], ALf[mi][1], ALf[mi][2], ALf[mi][3], a + A_SPLIT_B);
            }
            uint32_t BHf[4][4], BLf[4][4];
#pragma unroll
            for (int g = 0; g < 4; ++g) {
                int row = wn * 64 + g * 16 + lrow;
                uint32_t a = stage + 2 * A_SPLIT_B + sw_off(row, cc);
                LDSM_X4(BHf[g][0], BHf[g][1], BHf[g][2], BHf[g][3], a);
                LDSM_X4(BLf[g][0], BLf[g][1], BLf[g][2], BLf[g][3], a + B_SPLIT_B);
            }
            // 3 independent product sweeps (no back-to-back same-acc HMMA)
#pragma unroll
            for (int mi = 0; mi < 4; ++mi)
#pragma unroll
                for (int ni = 0; ni < 8; ++ni)
                    MMA_BF16(acc[mi][ni], AHf[mi], BHf[ni>>1][ni&1], BHf[ni>>1][(ni&1)+2]);
#pragma unroll
            for (int mi = 0; mi < 4; ++mi)
#pragma unroll
                for (int ni = 0; ni < 8; ++ni)
                    MMA_BF16(acc[mi][ni], AHf[mi], BLf[ni>>1][ni&1], BLf[ni>>1][(ni&1)+2]);
#pragma unroll
            for (int mi = 0; mi < 4; ++mi)
#pragma unroll
                for (int ni = 0; ni < 8; ++ni)
                    MMA_BF16(acc[mi][ni], ALf[mi], BHf[ni>>1][ni&1], BHf[ni>>1][(ni&1)+2]);
        }
    }

#pragma unroll
    for (int mi = 0; mi < 4; ++mi) {
        const int row = m0 + wm * 64 + mi * 16 + (lane >> 2);
#pragma unroll
        for (int ni = 0; ni < 8; ++ni) {
            const int col = nb + wn * 64 + ni * 8 + (lane & 3) * 2;
            float* cp = C + (size_t)row * Nc + col;
            *(float2*)cp = make_float2(acc[mi][ni][0], acc[mi][ni][1]);
            *(float2*)(cp + (size_t)8 * Nc) = make_float2(acc[mi][ni][2], acc[mi][ni][3]);
        }
    }
}

// ---------------- RoPE table (double precision trig) ------------------------
__global__ void rope_table_kernel()
{
    int idx = blockIdx.x * blockDim.x + threadIdx.x;
    if (idx >= S_ * 64) return;
    int s = idx >> 6, i = idx & 63;
    double inv = pow(10000.0, -(double)(2 * i) / 128.0);
    double f = (double)s * inv;
    g_cos[idx] = (float)cos(f);
    g_sin[idx] = (float)sin(f);
}

// ---------------- RoPE + bf16 split (q or k), fused -------------------------
__global__ void rope_split_qk(int which, int nheads, int total)
{
    int idx = blockIdx.x * blockDim.x + threadIdx.x;
    if (idx >= total) return;
    int j = idx & 31;
    int h = (idx >> 5) % nheads;
    int m = idx / (32 * nheads);
    int s = m & (S_ - 1);
    const float* src = (which == 1) ? g_q : g_k;
    __nv_bfloat16* dh = (which == 1) ? g_qh : g_kh;
    __nv_bfloat16* dl = (which == 1) ? g_ql : g_kl;
    size_t base = ((size_t)m * nheads + h) * HD_;
    int c0 = 2 * j;
    float2 x1 = *(const float2*)(src + base + c0);
    float2 x2 = *(const float2*)(src + base + c0 + 64);
    float2 cs = *(const float2*)(g_cos + s * 64 + c0);
    float2 sn = *(const float2*)(g_sin + s * 64 + c0);
    float y1x = x1.x * cs.x - x2.x * sn.x;
    float y1y = x1.y * cs.y - x2.y * sn.y;
    float y2x = x2.x * cs.x + x1.x * sn.x;
    float y2y = x2.y * cs.y + x1.y * sn.y;
    store_split2(dh + base + c0,      dl + base + c0,      y1x, y1y);
    store_split2(dh + base + c0 + 64, dl + base + c0 + 64, y2x, y2y);
}

// ---------------- V transpose + split: g_v -> vth/vtl [b][hk][hd][s] ---------
__global__ __launch_bounds__(256) void split_v_t()
{
    __shared__ float t[32][33];
    int tx = threadIdx.x & 31, ty = threadIdx.x >> 5;
    int s0 = blockIdx.x * 32, d0 = blockIdx.y * 32;
    int bz = blockIdx.z; int b = bz >> 2, hk = bz & 3;
#pragma unroll
    for (int rr = 0; rr < 4; ++rr) {
        int s = s0 + ty + 8 * rr;
        t[ty + 8 * rr][tx] = g_v[((size_t)(b * S_ + s) * NKV_ + hk) * HD_ + d0 + tx];
    }
    __syncthreads();
#pragma unroll
    for (int rr = 0; rr < 4; ++rr) {
        int d = d0 + ty + 8 * rr;
        float x = t[tx][ty + 8 * rr];
        __nv_bfloat16 hv = __float2bfloat16(x);
        size_t o = ((size_t)(b * NKV_ + hk) * HD_ + d) * S_ + s0 + tx;
        g_vth[o] = hv;
        g_vtl[o] = __float2bfloat16(x - __bfloat162float(hv));
    }
}

// ---------------- tensor-core causal flash attention (bf16x3) ----------------
// CTA: 128 q-rows, 8 warps x 16 rows. K/V tiles of 64, double-buffered cp.async.
// smem: Qh/Ql 64K | K bufs 2x32K | Vt bufs 2x32K = 192K.
#define FLASH_SMEM 196608

__global__ __launch_bounds__(256) void flash_tc()
{
    extern __shared__ char smem[];
    const uint32_t sb = smem_u32(smem);
    const int tid = threadIdx.x;
    const int wid = tid >> 5, lane = tid & 31;
    const int lrow = lane & 15, lchunk = lane >> 4;
    const int qb = (int)gridDim.x - 1 - (int)blockIdx.x;   // big blocks first
    const int h = blockIdx.y, b = blockIdx.z;
    const int hk = h >> 2;
    const int q0 = qb * 128;
    const int wq0 = wid * 16;

    // Q tile load (once): 2 splits x 128 rows x 256B = 4096 chunks
#pragma unroll
    for (int i = 0; i < 16; ++i) {
        int ch = tid + (i << 8);
        int sp = ch >> 11, w = ch & 2047;
        int r = w >> 4, c16 = w & 15;
        const __nv_bfloat16* src = (sp ? g_ql : g_qh)
            + ((size_t)((b * S_ + q0 + r) * NH_ + h)) * HD_ + c16 * 8;
        CP_ASYNC16(sb + sp * 32768 + (c16 >> 2) * 8192 + sw_off(r, c16 & 3), src);
    }
    CP_COMMIT();

    auto load_kv = [&](int jb, int s) {
        const int j0 = jb * 64;
        const uint32_t kb = sb + 65536 + s * 32768;
        const uint32_t vb = sb + 131072 + s * 32768;
#pragma unroll
        for (int i = 0; i < 16; ++i) {
            int ch = tid + (i << 8);
            if (ch < 2048) {                       // K: 2 splits x 64 rows x 16 chunks
                int sp = ch >> 10, w = ch & 1023;
                int r = w >> 4, c16 = w & 15;
                const __nv_bfloat16* src = (sp ? g_kl : g_kh)
                    + ((size_t)((b * S_ + j0 + r) * NKV_ + hk)) * HD_ + c16 * 8;
                CP_ASYNC16(kb + sp * 16384 + (c16 >> 2) * 4096 + sw_off(r, c16 & 3), src);
            } else {                               // Vt: 2 splits x 128 rows x 8 chunks
                int ch2 = ch - 2048;
                int sp = ch2 >> 10, w = ch2 & 1023;
                int d = w >> 3, c8 = w & 7;
                const __nv_bfloat16* src = (sp ? g_vtl : g_vth)
                    + ((size_t)(b * NKV_ + hk) * HD_ + d) * S_ + j0 + c8 * 8;
                CP_ASYNC16(vb + sp * 16384 + (c8 >> 2) * 8192 + sw_off(d, c8 & 3), src);
            }
        }
        CP_COMMIT();
    };

    load_kv(0, 0);

    float oacc[16][4];
#pragma unroll
    for (int ob = 0; ob < 16; ++ob)
#pragma unroll
        for (int e = 0; e < 4; ++e) oacc[ob][e] = 0.f;
    float m1 = -INFINITY, m2 = -INFINITY, l1 = 0.f, l2 = 0.f;
    const float scale2 = 0.12751726f;              // log2(e)/sqrt(128)
    const int r1g = q0 + wq0 + (lane >> 2);
    const int njb = 2 * qb + 2;

    for (int jb = 0; jb < njb; ++jb) {
        if (jb + 1 < njb) { load_kv(jb + 1, (jb + 1) & 1); CP_WAIT1(); }
        else              { CP_WAIT0(); }
        __syncthreads();
        const uint32_t kb = sb + 65536 + (jb & 1) * 32768;
        const uint32_t vb = sb + 131072 + (jb & 1) * 32768;
        const int j0 = jb * 64;

        if (j0 <= q0 + wq0 + 15) {                 // warp has unmasked work
            // ---- S = Q K^T (bf16x3)
            float sacc[8][4];
#pragma unroll
            for (int nb = 0; nb < 8; ++nb)
#pragma unroll
                for (int e = 0; e < 4; ++e) sacc[nb][e] = 0.f;

#pragma unroll
            for (int kk = 0; kk < 8; ++kk) {
                const int p = kk >> 1, cc = ((kk & 1) << 1) + lchunk;
                uint32_t AH[4], AL[4];
                uint32_t qa = sb + p * 8192 + sw_off(wq0 + lrow, cc);
                LDSM_X4(AH[0], AH[1], AH[2], AH[3], qa);
                LDSM_X4(AL[0], AL[1], AL[2], AL[3], qa + 32768);
                uint32_t KH[4][4], KL[4][4];
#pragma unroll
                for (int g = 0; g < 4; ++g) {
                    uint32_t ka = kb + p * 4096 + sw_off(g * 16 + lrow, cc);
                    LDSM_X4(KH[g][0], KH[g][1], KH[g][2], KH[g][3], ka);
                    LDSM_X4(KL[g][0], KL[g][1], KL[g][2], KL[g][3], ka + 16384);
                }
#pragma unroll
                for (int nb = 0; nb < 8; ++nb)
                    MMA_BF16(sacc[nb], AH, KH[nb>>1][nb&1], KH[nb>>1][(nb&1)+2]);
#pragma unroll
                for (int nb = 0; nb < 8; ++nb)
                    MMA_BF16(sacc[nb], AH, KL[nb>>1][nb&1], KL[nb>>1][(nb&1)+2]);
#pragma unroll
                for (int nb = 0; nb < 8; ++nb)
                    MMA_BF16(sacc[nb], AL, KH[nb>>1][nb&1], KH[nb>>1][(nb&1)+2]);
            }

            // ---- online softmax (exp2 domain)
            const bool msk = (j0 + 63 > q0 + wq0);
            float mx1 = -INFINITY, mx2 = -INFINITY;
#pragma unroll
            for (int nb = 0; nb < 8; ++nb) {
                int c0 = j0 + nb * 8 + ((lane & 3) << 1);
                float x0 = sacc[nb][0] * scale2, x1 = sacc[nb][1] * scale2;
                float x2 = sacc[nb][2] * scale2, x3 = sacc[nb][3] * scale2;
                if (msk) {
                    if (c0     > r1g)     x0 = -INFINITY;
                    if (c0 + 1 > r1g)     x1 = -INFINITY;
                    if (c0     > r1g + 8) x2 = -INFINITY;
                    if (c0 + 1 > r1g + 8) x3 = -INFINITY;
                }
                sacc[nb][0] = x0; sacc[nb][1] = x1; sacc[nb][2] = x2; sacc[nb][3] = x3;
                mx1 = fmaxf(mx1, fmaxf(x0, x1));
                mx2 = fmaxf(mx2, fmaxf(x2, x3));
            }
            mx1 = fmaxf(mx1, __shfl_xor_sync(0xffffffffu, mx1, 1));
            mx1 = fmaxf(mx1, __shfl_xor_sync(0xffffffffu, mx1, 2));
            mx2 = fmaxf(mx2, __shfl_xor_sync(0xffffffffu, mx2, 1));
            mx2 = fmaxf(mx2, __shfl_xor_sync(0xffffffffu, mx2, 2));
            float mn1 = fmaxf(m1, mx1), mn2 = fmaxf(m2, mx2);
            float cr1 = exp2f(m1 - mn1), cr2 = exp2f(m2 - mn2);
            float rs1 = 0.f, rs2 = 0.f;
#pragma unroll
            for (int nb = 0; nb < 8; ++nb) {
                float p0 = exp2f(sacc[nb][0] - mn1), p1 = exp2f(sacc[nb][1] - mn1);
                float p2 = exp2f(sacc[nb][2] - mn2), p3 = exp2f(sacc[nb][3] - mn2);
                sacc[nb][0] = p0; sacc[nb][1] = p1; sacc[nb][2] = p2; sacc[nb][3] = p3;
                rs1 += p0 + p1; rs2 += p2 + p3;
            }
            rs1 += __shfl_xor_sync(0xffffffffu, rs1, 1);
            rs1 += __shfl_xor_sync(0xffffffffu, rs1, 2);
            rs2 += __shfl_xor_sync(0xffffffffu, rs2, 1);
            rs2 += __shfl_xor_sync(0xffffffffu, rs2, 2);
            l1 = l1 * cr1 + rs1; l2 = l2 * cr2 + rs2;
            m1 = mn1; m2 = mn2;
#pragma unroll
            for (int ob = 0; ob < 16; ++ob) {
                oacc[ob][0] *= cr1; oacc[ob][1] *= cr1;
                oacc[ob][2] *= cr2; oacc[ob][3] *= cr2;
            }

            // ---- O += P V (bf16x3, P from registers)
#pragma unroll
            for (int kc = 0; kc < 4; ++kc) {
                uint32_t PH[4], PL[4];
                split_pack(sacc[2*kc][0],   sacc[2*kc][1],   PH[0], PL[0]);
                split_pack(sacc[2*kc][2],   sacc[2*kc][3],   PH[1], PL[1]);
                split_pack(sacc[2*kc+1][0], sacc[2*kc+1][1], PH[2], PL[2]);
                split_pack(sacc[2*kc+1][2], sacc[2*kc+1][3], PH[3], PL[3]);
                const int p = kc >> 1, cc = ((kc & 1) << 1) + lchunk;
#pragma unroll
                for (int g = 0; g < 8; ++g) {
                    uint32_t VH[4], VL[4];
                    uint32_t va = vb + p * 8192 + sw_off(g * 16 + lrow, cc);
                    LDSM_X4(VH[0], VH[1], VH[2], VH[3], va);
                    LDSM_X4(VL[0], VL[1], VL[2], VL[3], va + 16384);
                    MMA_BF16(oacc[2*g],   PH, VH[0], VH[2]);
                    MMA_BF16(oacc[2*g+1], PH, VH[1], VH[3]);
                    MMA_BF16(oacc[2*g],   PH, VL[0], VL[2]);
                    MMA_BF16(oacc[2*g+1], PH, VL[1], VL[3]);
                    MMA_BF16(oacc[2*g],   PL, VH[0], VH[2]);
                    MMA_BF16(oacc[2*g+1], PL, VH[1], VH[3]);
                }
            }
        }
        __syncthreads();
    }

    // ---- epilogue: normalize + split-write to aoh/aol
    float i1 = 1.f / l1, i2 = 1.f / l2;
    size_t base1 = (size_t)(b * S_ + r1g) * 2048 + h * 128;
    size_t base2 = base1 + (size_t)8 * 2048;
#pragma unroll
    for (int ob = 0; ob < 16; ++ob) {
        int col = ob * 8 + ((lane & 3) << 1);
        store_split2(g_aoh + base1 + col, g_aol + base1 + col,
                     oacc[ob][0] * i1, oacc[ob][1] * i1);
        store_split2(g_aoh + base2 + col, g_aol + base2 + col,
                     oacc[ob][2] * i2, oacc[ob][3] * i2);
    }
}

// ---------------- launch ----------------------------------------------------
extern "C" void kernel_launch(void* const* d_in, const int* in_sizes, int n_in,
                              void* d_out, int out_size)
{
    (void)in_sizes; (void)n_in; (void)out_size;
    const float* hs = (const float*)d_in[0];
    const float* Wq = (const float*)d_in[1];
    const float* Wk = (const float*)d_in[2];
    const float* Wv = (const float*)d_in[3];
    const float* Wo = (const float*)d_in[4];
    float* out = (float*)d_out;

    cudaFuncSetAttribute(tc_gemm, cudaFuncAttributeMaxDynamicSharedMemorySize, GEMM_SMEM);
    cudaFuncSetAttribute(flash_tc, cudaFuncAttributeMaxDynamicSharedMemorySize, FLASH_SMEM);

    // launches 1-5: splits  (launch #6 = fused QKV GEMM -> ncu -s 5 profiles it)
    { int n = M_ * H_;   split_bf16<<<n / 4 / 256, 256>>>(hs, 0, n); }
    { int n = 2048 * H_; split_bf16<<<n / 4 / 256, 256>>>(Wq, 1, n); }
    { int n = 512 * H_;  split_bf16<<<n / 4 / 256, 256>>>(Wk, 2, n); }
    { int n = 512 * H_;  split_bf16<<<n / 4 / 256, 256>>>(Wv, 3, n); }
    { int n = 2048 * H_; split_bf16<<<n / 4 / 256, 256>>>(Wo, 4, n); }

    // #6: fused QKV projection
    tc_gemm<<<dim3(24, 16), 256, GEMM_SMEM>>>(0, nullptr);

    // #7: rope table; #8/#9: fused rope+split; #10: V transpose-split
    rope_table_kernel<<<(S_ * 64 + 255) / 256, 256>>>();
    { int t = M_ * NH_ * 32;  rope_split_qk<<<(t + 255) / 256, 256>>>(1, NH_, t); }
    { int t = M_ * NKV_ * 32; rope_split_qk<<<(t + 255) / 256, 256>>>(2, NKV_, t); }
    split_v_t<<<dim3(S_ / 32, HD_ / 32, B_ * NKV_), 256>>>();

    // #11: tensor-core flash attention
    flash_tc<<<dim3(S_ / 128, NH_, B_), 256, FLASH_SMEM>>>();

    // #12: output projection
    tc_gemm<<<dim3(16, 16), 256, GEMM_SMEM>>>(1, out);
}